// round 12
// baseline (speedup 1.0000x reference)
#include <cuda_runtime.h>
#include <cuda_fp16.h>
#include <math.h>
#include <stdint.h>

// Problem constants
#define N_TOK   131072      // 32 * 4096 tokens
#define DIM     64
#define KCODES  1024
#define TT      128         // tokens per CTA
#define CH      64          // codes per chunk
#define NCH     (KCODES / CH)   // 16
#define NB      (N_TOK / TT)    // 1024 CTAs
#define NTHREADS 256
#define WDT_STR 68          // u32 stride per j row (272B, 16B-multiple)
#define WD_BUF  (64 * WDT_STR)  // u32 per W buffer

// Sound screen margin: > 2 * worst-case |fp16_dist - fp32_dist| (~2*4e-3
// pessimistic). Candidate count stays small (code-gap sigma ~9e-3).
#define MARGIN  1e-2f

#define QCAP    2048

// smem layout (4-byte offsets)
#define OFF_XH     0                     // xh[64][68] u32 (half2 tok-pairs) 4352
#define OFF_WD     4352                  // wd[2][64][68] u32 dup half2     8704
#define OFF_WSQ    13056                 // 1024
#define OFF_XSQ    14080                 // 128
#define OFF_BEST   14208                 // 128 u64 (8B aligned)            256
#define OFF_QCNT   14464                 // 4
#define OFF_QUEUE  14468                 // 2048
#define OFF_FIDX   16516                 // 128
#define OFF_RED    16644                 // 256
#define SMEM_WORDS 16900
#define SMEM_BYTES (SMEM_WORDS * 4)      // 67600 B -> 3 CTAs/SM

// Scratch
__device__ float    g_wsq[KCODES];
__device__ int      g_counts[KCODES];
__device__ float    g_part[NB];
__device__ uint32_t g_whdT[DIM * KCODES];   // [j][k] = (w_kj, w_kj) half2 bits

__device__ __forceinline__ uint32_t smem_u32(const void* p) {
    uint32_t a;
    asm("{ .reg .u64 t; cvta.to.shared.u64 t, %1; cvt.u32.u64 %0, t; }"
        : "=r"(a) : "l"(p));
    return a;
}

#define CP_ASYNC16(dst_u32, src_gptr) \
    asm volatile("cp.async.ca.shared.global [%0], [%1], 16;" \
                 :: "r"(dst_u32), "l"(src_gptr) : "memory")
#define CP_COMMIT() asm volatile("cp.async.commit_group;" ::: "memory")
#define CP_WAIT0()  asm volatile("cp.async.wait_group 0;"  ::: "memory")

__device__ __forceinline__ uint32_t h2_bits(__half2 h) {
    return *reinterpret_cast<uint32_t*>(&h);
}
__device__ __forceinline__ __half2 bits_h2(uint32_t u) {
    return *reinterpret_cast<__half2*>(&u);
}

// Exact distance, R1's PROVEN accumulation: sequential fmaf chain j=0..63,
// then fmaf(-2, dot, base). Matched reference argmin bit-for-bit.
__device__ __forceinline__ float exact_dist(const float* __restrict__ xrow,
                                            const float* __restrict__ wrow,
                                            float base) {
    float dot = 0.f;
    #pragma unroll
    for (int j = 0; j < DIM; ++j)
        dot = fmaf(wrow[j], xrow[j], dot);
    return fmaf(-2.f, dot, base);
}

// Warp-aggregated queue append (R6-proven).
__device__ __forceinline__ void queue_append(
    int cond, uint32_t entry, int* qcount, uint32_t* queue,
    const float* xrow_g, const float* wrow_g, float base, uint32_t gcode,
    unsigned long long* bestp)
{
    unsigned m = __ballot_sync(0xffffffffu, cond);
    if (cond) {
        int lane   = threadIdx.x & 31;
        int leader = __ffs(m) - 1;
        int rank   = __popc(m & ((1u << lane) - 1u));
        int basep  = 0;
        if (lane == leader) basep = atomicAdd(qcount, __popc(m));
        basep = __shfl_sync(m, basep, leader);
        int slot = basep + rank;
        if (slot < QCAP) {
            queue[slot] = entry;
        } else {                          // overflow (statistically never)
            float d = exact_dist(xrow_g, wrow_g, base);
            unsigned long long key =
                ((unsigned long long)__float_as_uint(d) << 32) | gcode;
            atomicMin(bestp, key);
        }
    }
}

// ---------------------------------------------------------------------------
// Kernel 0: wsq + counts + duplicated/transposed fp16 codebook g_whdT[j][k]
// ---------------------------------------------------------------------------
__global__ void vq_prep(const float* __restrict__ W) {
    int k = blockIdx.x * blockDim.x + threadIdx.x;   // 4 blocks x 256
    if (k < KCODES) {
        const float* row = W + (size_t)k * DIM;
        float s = 0.f;
        #pragma unroll
        for (int j = 0; j < DIM; ++j) {
            float v = row[j];
            s += v * v;
            __half h = __float2half_rn(v);
            __half2 d2 = __halves2half2(h, h);
            g_whdT[j * KCODES + k] = h2_bits(d2);    // coalesced across lanes
        }
        g_wsq[k]    = s;
        g_counts[k] = 0;
    }
}

// ---------------------------------------------------------------------------
// Kernel 1: HFMA2 fp16 screen (rt=2, no 64-bit bank trap) + queued exact refine
//   256 thr / 8 warps; tokens on lanes (4 = 2 half2 pairs), codes on warps (8).
// ---------------------------------------------------------------------------
__global__ void __launch_bounds__(NTHREADS)
vq_main(const float* __restrict__ x, const float* __restrict__ W,
        float* __restrict__ out)
{
    extern __shared__ uint32_t su[];
    uint32_t* xh    = su + OFF_XH;                    // [j][tp] half2 pairs
    uint32_t* wd    = su + OFF_WD;                    // [2][j][k] dup half2
    float*    wsq_s = (float*)(su + OFF_WSQ);
    float*    xsq_s = (float*)(su + OFF_XSQ);
    unsigned long long* best = (unsigned long long*)(su + OFF_BEST);
    int*      qcount = (int*)(su + OFF_QCNT);
    uint32_t* queue  = su + OFF_QUEUE;
    int*      fidx   = (int*)(su + OFF_FIDX);
    float*    red    = (float*)(su + OFF_RED);

    const int tid   = threadIdx.x;
    const int wid   = tid >> 5;
    const int lane  = tid & 31;
    const int tbase = blockIdx.x * TT;
    const int t0    = lane * 4;       // tokens t0..t0+3
    const int k0    = wid * 8;        // this warp's 8 codes per chunk

    const uint32_t wd_u = smem_u32(wd);

    if (tid == 0) *qcount = 0;
    if (tid < TT) best[tid] = 0xFFFFFFFFFFFFFFFFull;

    // ---- build fp16 token-pair tile xh[j][tp] ----
    for (int i = tid; i < 1024; i += NTHREADS) {
        int tp = i >> 4;                  // token pair 0..63
        int j4 = (i & 15) << 2;
        float4 va = *(const float4*)(x + (size_t)(tbase + 2 * tp) * DIM + j4);
        float4 vb = *(const float4*)(x + (size_t)(tbase + 2 * tp + 1) * DIM + j4);
        xh[(j4 + 0) * WDT_STR + tp] = h2_bits(__floats2half2_rn(va.x, vb.x));
        xh[(j4 + 1) * WDT_STR + tp] = h2_bits(__floats2half2_rn(va.y, vb.y));
        xh[(j4 + 2) * WDT_STR + tp] = h2_bits(__floats2half2_rn(va.z, vb.z));
        xh[(j4 + 3) * WDT_STR + tp] = h2_bits(__floats2half2_rn(va.w, vb.w));
    }
    for (int i = tid; i < KCODES; i += NTHREADS) wsq_s[i] = g_wsq[i];

    // ---- prefetch W chunk 0 (pre-dup'd, pre-transposed in global) ----
    for (int i = tid; i < 1024; i += NTHREADS) {      // 64 j x 16 segs
        int j = i >> 4, seg = i & 15;
        CP_ASYNC16(wd_u + (uint32_t)(j * WDT_STR + seg * 4) * 4,
                   g_whdT + (size_t)j * KCODES + seg * 4);
    }
    CP_COMMIT();

    // ---- xsq per token (sequential order, as R1/reference) ----
    if (tid < TT) {
        const float4* row = (const float4*)(x + (size_t)(tbase + tid) * DIM);
        float s = 0.f;
        #pragma unroll
        for (int q = 0; q < 16; ++q) {
            float4 v = row[q];
            s += v.x * v.x; s += v.y * v.y; s += v.z * v.z; s += v.w * v.w;
        }
        xsq_s[tid] = s;
    }
    __syncthreads();

    float xsqr[4];
    #pragma unroll
    for (int c = 0; c < 4; ++c) xsqr[c] = xsq_s[t0 + c];
    const float* xrow0g = x + (size_t)(tbase + t0) * DIM;   // for overflow path

    float rlb[4];
    #pragma unroll
    for (int c = 0; c < 4; ++c) rlb[c] = 3.0e38f;

    for (int ch = 0; ch < NCH; ++ch) {
        const int b = ch & 1;
        CP_WAIT0();
        __syncthreads();                  // chunk ch resident; qcount reset

        if (ch + 1 < NCH) {               // prefetch next chunk
            const uint32_t* src = g_whdT + (size_t)(ch + 1) * CH;
            const uint32_t dst0 = wd_u + (uint32_t)(((ch + 1) & 1) * WD_BUF) * 4;
            for (int i = tid; i < 1024; i += NTHREADS) {
                int j = i >> 4, seg = i & 15;
                CP_ASYNC16(dst0 + (uint32_t)(j * WDT_STR + seg * 4) * 4,
                           src + (size_t)j * KCODES + seg * 4);
            }
            CP_COMMIT();
        }

        const uint32_t* wb = wd + b * WD_BUF + k0;

        __half2 acc[2][8];
        #pragma unroll
        for (int p = 0; p < 2; ++p)
            #pragma unroll
            for (int k = 0; k < 8; ++k) acc[p][k] = __floats2half2_rn(0.f, 0.f);

        #pragma unroll 8
        for (int j = 0; j < DIM; ++j) {
            uint2 xv = *(const uint2*)(xh + j * WDT_STR + lane * 2);  // LDS.64
            __half2 xp0 = bits_h2(xv.x);          // tokens t0, t0+1
            __half2 xp1 = bits_h2(xv.y);          // tokens t0+2, t0+3
            uint4 wa = *(const uint4*)(wb + (size_t)j * WDT_STR);     // codes 0-3
            uint4 wc = *(const uint4*)(wb + (size_t)j * WDT_STR + 4); // codes 4-7
            acc[0][0] = __hfma2(bits_h2(wa.x), xp0, acc[0][0]);
            acc[1][0] = __hfma2(bits_h2(wa.x), xp1, acc[1][0]);
            acc[0][1] = __hfma2(bits_h2(wa.y), xp0, acc[0][1]);
            acc[1][1] = __hfma2(bits_h2(wa.y), xp1, acc[1][1]);
            acc[0][2] = __hfma2(bits_h2(wa.z), xp0, acc[0][2]);
            acc[1][2] = __hfma2(bits_h2(wa.z), xp1, acc[1][2]);
            acc[0][3] = __hfma2(bits_h2(wa.w), xp0, acc[0][3]);
            acc[1][3] = __hfma2(bits_h2(wa.w), xp1, acc[1][3]);
            acc[0][4] = __hfma2(bits_h2(wc.x), xp0, acc[0][4]);
            acc[1][4] = __hfma2(bits_h2(wc.x), xp1, acc[1][4]);
            acc[0][5] = __hfma2(bits_h2(wc.y), xp0, acc[0][5]);
            acc[1][5] = __hfma2(bits_h2(wc.y), xp1, acc[1][5]);
            acc[0][6] = __hfma2(bits_h2(wc.z), xp0, acc[0][6]);
            acc[1][6] = __hfma2(bits_h2(wc.z), xp1, acc[1][6]);
            acc[0][7] = __hfma2(bits_h2(wc.w), xp0, acc[0][7]);
            acc[1][7] = __hfma2(bits_h2(wc.w), xp1, acc[1][7]);
        }

        // ---- screen: approx dists, ballot-append candidates ----
        #pragma unroll
        for (int k = 0; k < 8; ++k) {
            const int lc = k0 + k;            // local code in chunk
            const int g  = ch * CH + lc;
            const float wsqk = wsq_s[g];
            float2 f0 = __half22float2(acc[0][k]);   // dots t0, t0+1
            float2 f1 = __half22float2(acc[1][k]);   // dots t0+2, t0+3
            float a0 = fmaf(-2.f, f0.x, wsqk + xsqr[0]);
            float a1 = fmaf(-2.f, f0.y, wsqk + xsqr[1]);
            float a2 = fmaf(-2.f, f1.x, wsqk + xsqr[2]);
            float a3 = fmaf(-2.f, f1.y, wsqk + xsqr[3]);
            const float* wg = W + (size_t)g * DIM;
            queue_append(a0 < rlb[0] + MARGIN, (uint32_t)(((t0 + 0) << 8) | lc),
                         qcount, queue, xrow0g,           wg, wsqk + xsqr[0],
                         (uint32_t)g, &best[t0 + 0]);
            queue_append(a1 < rlb[1] + MARGIN, (uint32_t)(((t0 + 1) << 8) | lc),
                         qcount, queue, xrow0g + DIM,     wg, wsqk + xsqr[1],
                         (uint32_t)g, &best[t0 + 1]);
            queue_append(a2 < rlb[2] + MARGIN, (uint32_t)(((t0 + 2) << 8) | lc),
                         qcount, queue, xrow0g + 2 * DIM, wg, wsqk + xsqr[2],
                         (uint32_t)g, &best[t0 + 2]);
            queue_append(a3 < rlb[3] + MARGIN, (uint32_t)(((t0 + 3) << 8) | lc),
                         qcount, queue, xrow0g + 3 * DIM, wg, wsqk + xsqr[3],
                         (uint32_t)g, &best[t0 + 3]);
            rlb[0] = fminf(rlb[0], a0);
            rlb[1] = fminf(rlb[1], a1);
            rlb[2] = fminf(rlb[2], a2);
            rlb[3] = fminf(rlb[3], a3);
        }

        __syncthreads();                  // appends visible

        // ---- cooperative bit-exact refine (x, W from global; L1/L2-hot) ----
        const int n = *qcount;
        const int nq = n < QCAP ? n : QCAP;
        for (int i = tid; i < nq; i += NTHREADS) {
            uint32_t e = queue[i];
            int t  = (int)(e >> 8);
            int lc = (int)(e & 255);
            int g  = ch * CH + lc;
            float base = wsq_s[g] + xsq_s[t];
            float d = exact_dist(x + (size_t)(tbase + t) * DIM,
                                 W + (size_t)g * DIM, base);
            unsigned long long key =
                ((unsigned long long)__float_as_uint(d) << 32) | (uint32_t)g;
            atomicMin(&best[t], key);
        }

        __syncthreads();                  // refine done
        if (tid == 0) *qcount = 0;
    }

    __syncthreads();
    if (tid < TT) {
        int bi = (int)(best[tid] & 0xFFFFFFFFull);
        fidx[tid] = bi;
        atomicAdd(&g_counts[bi], 1);
    }
    __syncthreads();

    // ---- epilogue: quantized_st (coalesced) + loss partial ----
    float ls = 0.f;
    for (int i = tid; i < TT * 16; i += NTHREADS) {
        int t  = i >> 4;
        int c4 = (i & 15) << 2;
        int kb = fidx[t];
        float4 w4 = *(const float4*)(W + (size_t)kb * DIM + c4);
        float4 xv = *(const float4*)(x + (size_t)(tbase + t) * DIM + c4);
        float4 o; float dq;
        dq = w4.x - xv.x; o.x = xv.x + dq; ls = fmaf(dq, dq, ls);
        dq = w4.y - xv.y; o.y = xv.y + dq; ls = fmaf(dq, dq, ls);
        dq = w4.z - xv.z; o.z = xv.z + dq; ls = fmaf(dq, dq, ls);
        dq = w4.w - xv.w; o.w = xv.w + dq; ls = fmaf(dq, dq, ls);
        *(float4*)(out + (size_t)(tbase + t) * DIM + c4) = o;
    }

    red[tid] = ls;
    __syncthreads();
    for (int off = NTHREADS / 2; off > 0; off >>= 1) {
        if (tid < off) red[tid] += red[tid + off];
        __syncthreads();
    }
    if (tid == 0) g_part[blockIdx.x] = red[0];
}

// ---------------------------------------------------------------------------
// Kernel 2: final scalars (loss, perplexity, usage)
// ---------------------------------------------------------------------------
__global__ void vq_final(float* __restrict__ out, int out_size) {
    __shared__ float red[1024];
    __shared__ float red2[1024];
    int tid = threadIdx.x;

    red[tid] = g_part[tid];
    __syncthreads();
    for (int off = 512; off > 0; off >>= 1) {
        if (tid < off) red[tid] += red[tid + off];
        __syncthreads();
    }
    float sse = red[0];
    __syncthreads();

    int c  = g_counts[tid];
    float p = (float)c / (float)N_TOK;
    red[tid]  = p * logf(p + 1e-10f);
    red2[tid] = (c >= 1) ? 1.f : 0.f;
    __syncthreads();
    for (int off = 512; off > 0; off >>= 1) {
        if (tid < off) { red[tid] += red[tid + off]; red2[tid] += red2[tid + off]; }
        __syncthreads();
    }
    if (tid == 0 && out_size >= N_TOK * DIM + 3) {
        float mse = sse / (float)(N_TOK * DIM);
        out[N_TOK * DIM + 0] = mse + 2.0f * mse;   // q_latent + COMMITMENT_COST*e_latent
        out[N_TOK * DIM + 1] = expf(-red[0]);
        out[N_TOK * DIM + 2] = red2[0];
    }
}

// ---------------------------------------------------------------------------
extern "C" void kernel_launch(void* const* d_in, const int* in_sizes, int n_in,
                              void* d_out, int out_size) {
    const float* x = (const float*)d_in[0];   // [32,4096,64] f32
    const float* W = (const float*)d_in[1];   // [1024,64] f32
    float* out = (float*)d_out;

    cudaFuncSetAttribute(vq_main, cudaFuncAttributeMaxDynamicSharedMemorySize,
                         SMEM_BYTES);

    vq_prep<<<4, 256>>>(W);
    vq_main<<<NB, NTHREADS, SMEM_BYTES>>>(x, W, out);
    vq_final<<<1, 1024>>>(out, out_size);
}

// round 13
// speedup vs baseline: 1.7822x; 1.7822x over previous
#include <cuda_runtime.h>
#include <cuda_fp16.h>
#include <math.h>
#include <stdint.h>

// Problem constants
#define N_TOK   131072      // 32 * 4096 tokens
#define DIM     64
#define KCODES  1024
#define TT      128         // tokens per CTA
#define CH      64          // codes per chunk
#define NCH     (KCODES / CH)   // 16
#define NB      (N_TOK / TT)    // 1024 CTAs
#define NTHREADS 256
#define WDT_STR 68          // u32 stride per j row (272B, 16B-multiple)
#define WD_BUF  (64 * WDT_STR)  // u32 per W buffer

// Sound screen margin: worst-case |fp16_dist - fp32_dist| <= ~1.5e-3
// (conversion 8e-5 + fp16 accumulation worst 1.4e-3); need margin >= 2x.
// Per-token distance spread sigma ~1.3e-2 -> ~2 near-tie candidates/token.
#define MARGIN  5e-3f

#define QCAP    2048

// smem layout (4-byte offsets)
#define OFF_XH     0                     // xh[64][68] u32 (half2 tok-pairs) 4352
#define OFF_WD     4352                  // wd[2][64][68] u32 dup half2     8704
#define OFF_WSQ    13056                 // 1024
#define OFF_XSQ    14080                 // 128
#define OFF_BEST   14208                 // 128 u64 (8B aligned)            256
#define OFF_QCNT   14464                 // 4
#define OFF_QUEUE  14468                 // 2048
#define OFF_FIDX   16516                 // 128
#define OFF_RED    16644                 // 256
#define SMEM_WORDS 16900
#define SMEM_BYTES (SMEM_WORDS * 4)      // 67600 B -> 3 CTAs/SM

// Scratch
__device__ float    g_wsq[KCODES];
__device__ int      g_counts[KCODES];
__device__ float    g_part[NB];
__device__ uint32_t g_whdT[DIM * KCODES];   // [j][k] = (w_kj, w_kj) half2 bits

__device__ __forceinline__ uint32_t smem_u32(const void* p) {
    uint32_t a;
    asm("{ .reg .u64 t; cvta.to.shared.u64 t, %1; cvt.u32.u64 %0, t; }"
        : "=r"(a) : "l"(p));
    return a;
}

#define CP_ASYNC16(dst_u32, src_gptr) \
    asm volatile("cp.async.ca.shared.global [%0], [%1], 16;" \
                 :: "r"(dst_u32), "l"(src_gptr) : "memory")
#define CP_COMMIT() asm volatile("cp.async.commit_group;" ::: "memory")
#define CP_WAIT0()  asm volatile("cp.async.wait_group 0;"  ::: "memory")

__device__ __forceinline__ uint32_t h2_bits(__half2 h) {
    return *reinterpret_cast<uint32_t*>(&h);
}
__device__ __forceinline__ __half2 bits_h2(uint32_t u) {
    return *reinterpret_cast<__half2*>(&u);
}

// Exact distance, R1's PROVEN accumulation: sequential fmaf chain j=0..63,
// then fmaf(-2, dot, base). Matched reference argmin bit-for-bit.
__device__ __forceinline__ float exact_dist(const float* __restrict__ xrow,
                                            const float* __restrict__ wrow,
                                            float base) {
    float dot = 0.f;
    #pragma unroll
    for (int j = 0; j < DIM; ++j)
        dot = fmaf(wrow[j], xrow[j], dot);
    return fmaf(-2.f, dot, base);
}

// Warp-aggregated queue append (R6-proven).
__device__ __forceinline__ void queue_append(
    int cond, uint32_t entry, int* qcount, uint32_t* queue,
    const float* xrow_g, const float* wrow_g, float base, uint32_t gcode,
    unsigned long long* bestp)
{
    unsigned m = __ballot_sync(0xffffffffu, cond);
    if (cond) {
        int lane   = threadIdx.x & 31;
        int leader = __ffs(m) - 1;
        int rank   = __popc(m & ((1u << lane) - 1u));
        int basep  = 0;
        if (lane == leader) basep = atomicAdd(qcount, __popc(m));
        basep = __shfl_sync(m, basep, leader);
        int slot = basep + rank;
        if (slot < QCAP) {
            queue[slot] = entry;
        } else {                          // overflow (25x headroom; ~never)
            float d = exact_dist(xrow_g, wrow_g, base);
            unsigned long long key =
                ((unsigned long long)__float_as_uint(d) << 32) | gcode;
            atomicMin(bestp, key);
        }
    }
}

// ---------------------------------------------------------------------------
// Kernel 0: wsq + counts + duplicated/transposed fp16 codebook g_whdT[j][k]
// ---------------------------------------------------------------------------
__global__ void vq_prep(const float* __restrict__ W) {
    int k = blockIdx.x * blockDim.x + threadIdx.x;   // 4 blocks x 256
    if (k < KCODES) {
        const float* row = W + (size_t)k * DIM;
        float s = 0.f;
        #pragma unroll
        for (int j = 0; j < DIM; ++j) {
            float v = row[j];
            s += v * v;
            __half h = __float2half_rn(v);
            __half2 d2 = __halves2half2(h, h);
            g_whdT[j * KCODES + k] = h2_bits(d2);    // coalesced across lanes
        }
        g_wsq[k]    = s;
        g_counts[k] = 0;
    }
}

// ---------------------------------------------------------------------------
// Kernel 1: HFMA2 fp16 screen (rt=2) + queued bit-exact fp32 refine
//   256 thr / 8 warps; tokens on lanes (4 = 2 half2 pairs), codes on warps (8).
// ---------------------------------------------------------------------------
__global__ void __launch_bounds__(NTHREADS)
vq_main(const float* __restrict__ x, const float* __restrict__ W,
        float* __restrict__ out)
{
    extern __shared__ uint32_t su[];
    uint32_t* xh    = su + OFF_XH;                    // [j][tp] half2 pairs
    uint32_t* wd    = su + OFF_WD;                    // [2][j][k] dup half2
    float*    wsq_s = (float*)(su + OFF_WSQ);
    float*    xsq_s = (float*)(su + OFF_XSQ);
    unsigned long long* best = (unsigned long long*)(su + OFF_BEST);
    int*      qcount = (int*)(su + OFF_QCNT);
    uint32_t* queue  = su + OFF_QUEUE;
    int*      fidx   = (int*)(su + OFF_FIDX);
    float*    red    = (float*)(su + OFF_RED);

    const int tid   = threadIdx.x;
    const int wid   = tid >> 5;
    const int lane  = tid & 31;
    const int tbase = blockIdx.x * TT;
    const int t0    = lane * 4;       // tokens t0..t0+3
    const int k0    = wid * 8;        // this warp's 8 codes per chunk

    const uint32_t wd_u = smem_u32(wd);

    if (tid == 0) *qcount = 0;
    if (tid < TT) best[tid] = 0xFFFFFFFFFFFFFFFFull;

    // ---- build fp16 token-pair tile xh[j][tp] ----
    for (int i = tid; i < 1024; i += NTHREADS) {
        int tp = i >> 4;                  // token pair 0..63
        int j4 = (i & 15) << 2;
        float4 va = *(const float4*)(x + (size_t)(tbase + 2 * tp) * DIM + j4);
        float4 vb = *(const float4*)(x + (size_t)(tbase + 2 * tp + 1) * DIM + j4);
        xh[(j4 + 0) * WDT_STR + tp] = h2_bits(__floats2half2_rn(va.x, vb.x));
        xh[(j4 + 1) * WDT_STR + tp] = h2_bits(__floats2half2_rn(va.y, vb.y));
        xh[(j4 + 2) * WDT_STR + tp] = h2_bits(__floats2half2_rn(va.z, vb.z));
        xh[(j4 + 3) * WDT_STR + tp] = h2_bits(__floats2half2_rn(va.w, vb.w));
    }
    for (int i = tid; i < KCODES; i += NTHREADS) wsq_s[i] = g_wsq[i];

    // ---- prefetch W chunk 0 (pre-dup'd, pre-transposed in global) ----
    for (int i = tid; i < 1024; i += NTHREADS) {      // 64 j x 16 segs
        int j = i >> 4, seg = i & 15;
        CP_ASYNC16(wd_u + (uint32_t)(j * WDT_STR + seg * 4) * 4,
                   g_whdT + (size_t)j * KCODES + seg * 4);
    }
    CP_COMMIT();

    // ---- xsq per token (sequential order, as R1/reference) ----
    if (tid < TT) {
        const float4* row = (const float4*)(x + (size_t)(tbase + tid) * DIM);
        float s = 0.f;
        #pragma unroll
        for (int q = 0; q < 16; ++q) {
            float4 v = row[q];
            s += v.x * v.x; s += v.y * v.y; s += v.z * v.z; s += v.w * v.w;
        }
        xsq_s[tid] = s;
    }
    __syncthreads();

    float xsqr[4];
    #pragma unroll
    for (int c = 0; c < 4; ++c) xsqr[c] = xsq_s[t0 + c];
    const float* xrow0g = x + (size_t)(tbase + t0) * DIM;   // for overflow path

    float rlb[4];
    #pragma unroll
    for (int c = 0; c < 4; ++c) rlb[c] = 3.0e38f;

    for (int ch = 0; ch < NCH; ++ch) {
        const int b = ch & 1;
        CP_WAIT0();
        __syncthreads();                  // chunk ch resident; qcount reset

        if (ch + 1 < NCH) {               // prefetch next chunk
            const uint32_t* src = g_whdT + (size_t)(ch + 1) * CH;
            const uint32_t dst0 = wd_u + (uint32_t)(((ch + 1) & 1) * WD_BUF) * 4;
            for (int i = tid; i < 1024; i += NTHREADS) {
                int j = i >> 4, seg = i & 15;
                CP_ASYNC16(dst0 + (uint32_t)(j * WDT_STR + seg * 4) * 4,
                           src + (size_t)j * KCODES + seg * 4);
            }
            CP_COMMIT();
        }

        const uint32_t* wb = wd + b * WD_BUF + k0;

        __half2 acc[2][8];
        #pragma unroll
        for (int p = 0; p < 2; ++p)
            #pragma unroll
            for (int k = 0; k < 8; ++k) acc[p][k] = __floats2half2_rn(0.f, 0.f);

        #pragma unroll 8
        for (int j = 0; j < DIM; ++j) {
            uint2 xv = *(const uint2*)(xh + j * WDT_STR + lane * 2);  // LDS.64
            __half2 xp0 = bits_h2(xv.x);          // tokens t0, t0+1
            __half2 xp1 = bits_h2(xv.y);          // tokens t0+2, t0+3
            uint4 wa = *(const uint4*)(wb + (size_t)j * WDT_STR);     // codes 0-3
            uint4 wc = *(const uint4*)(wb + (size_t)j * WDT_STR + 4); // codes 4-7
            acc[0][0] = __hfma2(bits_h2(wa.x), xp0, acc[0][0]);
            acc[1][0] = __hfma2(bits_h2(wa.x), xp1, acc[1][0]);
            acc[0][1] = __hfma2(bits_h2(wa.y), xp0, acc[0][1]);
            acc[1][1] = __hfma2(bits_h2(wa.y), xp1, acc[1][1]);
            acc[0][2] = __hfma2(bits_h2(wa.z), xp0, acc[0][2]);
            acc[1][2] = __hfma2(bits_h2(wa.z), xp1, acc[1][2]);
            acc[0][3] = __hfma2(bits_h2(wa.w), xp0, acc[0][3]);
            acc[1][3] = __hfma2(bits_h2(wa.w), xp1, acc[1][3]);
            acc[0][4] = __hfma2(bits_h2(wc.x), xp0, acc[0][4]);
            acc[1][4] = __hfma2(bits_h2(wc.x), xp1, acc[1][4]);
            acc[0][5] = __hfma2(bits_h2(wc.y), xp0, acc[0][5]);
            acc[1][5] = __hfma2(bits_h2(wc.y), xp1, acc[1][5]);
            acc[0][6] = __hfma2(bits_h2(wc.z), xp0, acc[0][6]);
            acc[1][6] = __hfma2(bits_h2(wc.z), xp1, acc[1][6]);
            acc[0][7] = __hfma2(bits_h2(wc.w), xp0, acc[0][7]);
            acc[1][7] = __hfma2(bits_h2(wc.w), xp1, acc[1][7]);
        }

        // ---- screen: approx dists, ballot-append candidates ----
        #pragma unroll
        for (int k = 0; k < 8; ++k) {
            const int lc = k0 + k;            // local code in chunk
            const int g  = ch * CH + lc;
            const float wsqk = wsq_s[g];
            float2 f0 = __half22float2(acc[0][k]);   // dots t0, t0+1
            float2 f1 = __half22float2(acc[1][k]);   // dots t0+2, t0+3
            float a0 = fmaf(-2.f, f0.x, wsqk + xsqr[0]);
            float a1 = fmaf(-2.f, f0.y, wsqk + xsqr[1]);
            float a2 = fmaf(-2.f, f1.x, wsqk + xsqr[2]);
            float a3 = fmaf(-2.f, f1.y, wsqk + xsqr[3]);
            const float* wg = W + (size_t)g * DIM;
            queue_append(a0 < rlb[0] + MARGIN, (uint32_t)(((t0 + 0) << 8) | lc),
                         qcount, queue, xrow0g,           wg, wsqk + xsqr[0],
                         (uint32_t)g, &best[t0 + 0]);
            queue_append(a1 < rlb[1] + MARGIN, (uint32_t)(((t0 + 1) << 8) | lc),
                         qcount, queue, xrow0g + DIM,     wg, wsqk + xsqr[1],
                         (uint32_t)g, &best[t0 + 1]);
            queue_append(a2 < rlb[2] + MARGIN, (uint32_t)(((t0 + 2) << 8) | lc),
                         qcount, queue, xrow0g + 2 * DIM, wg, wsqk + xsqr[2],
                         (uint32_t)g, &best[t0 + 2]);
            queue_append(a3 < rlb[3] + MARGIN, (uint32_t)(((t0 + 3) << 8) | lc),
                         qcount, queue, xrow0g + 3 * DIM, wg, wsqk + xsqr[3],
                         (uint32_t)g, &best[t0 + 3]);
            rlb[0] = fminf(rlb[0], a0);
            rlb[1] = fminf(rlb[1], a1);
            rlb[2] = fminf(rlb[2], a2);
            rlb[3] = fminf(rlb[3], a3);
        }

        __syncthreads();                  // appends visible

        // ---- cooperative bit-exact refine (x, W from global; L1/L2-hot) ----
        const int n = *qcount;
        const int nq = n < QCAP ? n : QCAP;
        for (int i = tid; i < nq; i += NTHREADS) {
            uint32_t e = queue[i];
            int t  = (int)(e >> 8);
            int lc = (int)(e & 255);
            int g  = ch * CH + lc;
            float base = wsq_s[g] + xsq_s[t];
            float d = exact_dist(x + (size_t)(tbase + t) * DIM,
                                 W + (size_t)g * DIM, base);
            unsigned long long key =
                ((unsigned long long)__float_as_uint(d) << 32) | (uint32_t)g;
            atomicMin(&best[t], key);
        }

        __syncthreads();                  // refine done
        if (tid == 0) *qcount = 0;
    }

    __syncthreads();
    if (tid < TT) {
        int bi = (int)(best[tid] & 0xFFFFFFFFull);
        fidx[tid] = bi;
        atomicAdd(&g_counts[bi], 1);
    }
    __syncthreads();

    // ---- epilogue: quantized_st (coalesced) + loss partial ----
    float ls = 0.f;
    for (int i = tid; i < TT * 16; i += NTHREADS) {
        int t  = i >> 4;
        int c4 = (i & 15) << 2;
        int kb = fidx[t];
        float4 w4 = *(const float4*)(W + (size_t)kb * DIM + c4);
        float4 xv = *(const float4*)(x + (size_t)(tbase + t) * DIM + c4);
        float4 o; float dq;
        dq = w4.x - xv.x; o.x = xv.x + dq; ls = fmaf(dq, dq, ls);
        dq = w4.y - xv.y; o.y = xv.y + dq; ls = fmaf(dq, dq, ls);
        dq = w4.z - xv.z; o.z = xv.z + dq; ls = fmaf(dq, dq, ls);
        dq = w4.w - xv.w; o.w = xv.w + dq; ls = fmaf(dq, dq, ls);
        *(float4*)(out + (size_t)(tbase + t) * DIM + c4) = o;
    }

    red[tid] = ls;
    __syncthreads();
    for (int off = NTHREADS / 2; off > 0; off >>= 1) {
        if (tid < off) red[tid] += red[tid + off];
        __syncthreads();
    }
    if (tid == 0) g_part[blockIdx.x] = red[0];
}

// ---------------------------------------------------------------------------
// Kernel 2: final scalars (loss, perplexity, usage)
// ---------------------------------------------------------------------------
__global__ void vq_final(float* __restrict__ out, int out_size) {
    __shared__ float red[1024];
    __shared__ float red2[1024];
    int tid = threadIdx.x;

    red[tid] = g_part[tid];
    __syncthreads();
    for (int off = 512; off > 0; off >>= 1) {
        if (tid < off) red[tid] += red[tid + off];
        __syncthreads();
    }
    float sse = red[0];
    __syncthreads();

    int c  = g_counts[tid];
    float p = (float)c / (float)N_TOK;
    red[tid]  = p * logf(p + 1e-10f);
    red2[tid] = (c >= 1) ? 1.f : 0.f;
    __syncthreads();
    for (int off = 512; off > 0; off >>= 1) {
        if (tid < off) { red[tid] += red[tid + off]; red2[tid] += red2[tid + off]; }
        __syncthreads();
    }
    if (tid == 0 && out_size >= N_TOK * DIM + 3) {
        float mse = sse / (float)(N_TOK * DIM);
        out[N_TOK * DIM + 0] = mse + 2.0f * mse;   // q_latent + COMMITMENT_COST*e_latent
        out[N_TOK * DIM + 1] = expf(-red[0]);
        out[N_TOK * DIM + 2] = red2[0];
    }
}

// ---------------------------------------------------------------------------
extern "C" void kernel_launch(void* const* d_in, const int* in_sizes, int n_in,
                              void* d_out, int out_size) {
    const float* x = (const float*)d_in[0];   // [32,4096,64] f32
    const float* W = (const float*)d_in[1];   // [1024,64] f32
    float* out = (float*)d_out;

    cudaFuncSetAttribute(vq_main, cudaFuncAttributeMaxDynamicSharedMemorySize,
                         SMEM_BYTES);

    vq_prep<<<4, 256>>>(W);
    vq_main<<<NB, NTHREADS, SMEM_BYTES>>>(x, W, out);
    vq_final<<<1, 1024>>>(out, out_size);
}

// round 14
// speedup vs baseline: 2.9594x; 1.6605x over previous
#include <cuda_runtime.h>
#include <cuda_fp16.h>
#include <math.h>
#include <stdint.h>

// Problem constants
#define N_TOK   131072      // 32 * 4096 tokens
#define DIM     64
#define KCODES  1024
#define TT      128         // tokens per CTA
#define CH      64          // codes per chunk
#define NCH     (KCODES / CH)   // 16
#define NB      (N_TOK / TT)    // 1024 CTAs
#define NTHREADS 256
#define WDT_STR 68          // u32 stride per j row (272B, 16B-multiple)
#define WD_BUF  (64 * WDT_STR)  // u32 per W buffer

// Screen error (split fp16 chains, fp32 combine): conversion ~1e-4 +
// 2x32-term fp16 accumulation ~2.4e-4 -> E <= ~3.5e-4. Soundness needs
// MARGIN >= 2E; 1e-3 is safely above.
#define MARGIN  1e-3f

#define QCAP    3072        // smem candidate queue
#define SPILLCAP 1024       // per-CTA global spill queue

// smem layout (4-byte offsets)
#define OFF_XH     0                     // xh[64][68] u32 (half2 tok-pairs) 4352
#define OFF_WD     4352                  // wd[2][64][68] u32 dup half2     8704
#define OFF_WSQ    13056                 // 1024
#define OFF_XSQ    14080                 // 128
#define OFF_BEST   14208                 // 128 u64 (8B aligned)            256
#define OFF_QCNT   14464                 // 1
#define OFF_SCNT   14465                 // 1 (+2 pad)
#define OFF_QUEUE  14468                 // 3072
#define OFF_FIDX   17540                 // 128
#define OFF_RED    17668                 // 256
#define SMEM_WORDS 17924
#define SMEM_BYTES (SMEM_WORDS * 4)      // 71696 B -> 3 CTAs/SM (215KB)

// Scratch
__device__ float    g_wsq[KCODES];
__device__ int      g_counts[KCODES];
__device__ float    g_part[NB];
__device__ uint32_t g_whdT[DIM * KCODES];     // [j][k] = (w,w) half2 bits
__device__ uint32_t g_spill[NB * SPILLCAP];   // overflow candidates (4MB)

__device__ __forceinline__ uint32_t smem_u32(const void* p) {
    uint32_t a;
    asm("{ .reg .u64 t; cvta.to.shared.u64 t, %1; cvt.u32.u64 %0, t; }"
        : "=r"(a) : "l"(p));
    return a;
}

#define CP_ASYNC16(dst_u32, src_gptr) \
    asm volatile("cp.async.ca.shared.global [%0], [%1], 16;" \
                 :: "r"(dst_u32), "l"(src_gptr) : "memory")
#define CP_COMMIT() asm volatile("cp.async.commit_group;" ::: "memory")
#define CP_WAIT0()  asm volatile("cp.async.wait_group 0;"  ::: "memory")

__device__ __forceinline__ uint32_t h2_bits(__half2 h) {
    return *reinterpret_cast<uint32_t*>(&h);
}
__device__ __forceinline__ __half2 bits_h2(uint32_t u) {
    return *reinterpret_cast<__half2*>(&u);
}

// Exact distance, R1's PROVEN accumulation: sequential fmaf chain j=0..63,
// then fmaf(-2, dot, base). Matched reference argmin bit-for-bit.
__device__ __forceinline__ float exact_dist(const float* __restrict__ xrow,
                                            const float* __restrict__ wrow,
                                            float base) {
    float dot = 0.f;
    #pragma unroll
    for (int j = 0; j < DIM; ++j)
        dot = fmaf(wrow[j], xrow[j], dot);
    return fmaf(-2.f, dot, base);
}

// Warp-aggregated candidate append: smem queue, then global spill.
// NEVER runs a divergent exact chain (R12/R13 pathology removed).
__device__ __forceinline__ void queue_append(
    int cond, uint32_t entry, int* qcount, int* scount, uint32_t* queue)
{
    unsigned m = __ballot_sync(0xffffffffu, cond);
    if (cond) {
        int lane   = threadIdx.x & 31;
        int leader = __ffs(m) - 1;
        int rank   = __popc(m & ((1u << lane) - 1u));
        int basep  = 0;
        if (lane == leader) basep = atomicAdd(qcount, __popc(m));
        basep = __shfl_sync(m, basep, leader);
        int slot = basep + rank;
        if (slot < QCAP) {
            queue[slot] = entry;
        } else {
            int ss = atomicAdd(scount, 1);
            if (ss < SPILLCAP)
                g_spill[(size_t)blockIdx.x * SPILLCAP + ss] = entry;
            // beyond SPILLCAP (4096+ cands/chunk) statistically impossible
        }
    }
}

// ---------------------------------------------------------------------------
// Kernel 0: wsq + counts + duplicated/transposed fp16 codebook g_whdT[j][k]
// ---------------------------------------------------------------------------
__global__ void vq_prep(const float* __restrict__ W) {
    int k = blockIdx.x * blockDim.x + threadIdx.x;   // 4 blocks x 256
    if (k < KCODES) {
        const float* row = W + (size_t)k * DIM;
        float s = 0.f;
        #pragma unroll
        for (int j = 0; j < DIM; ++j) {
            float v = row[j];
            s += v * v;
            __half h = __float2half_rn(v);
            __half2 d2 = __halves2half2(h, h);
            g_whdT[j * KCODES + k] = h2_bits(d2);    // coalesced across lanes
        }
        g_wsq[k]    = s;
        g_counts[k] = 0;
    }
}

// ---------------------------------------------------------------------------
// Kernel 1: HFMA2 screen (split fp16 chains) + queued bit-exact fp32 refine
// ---------------------------------------------------------------------------
__global__ void __launch_bounds__(NTHREADS, 3)
vq_main(const float* __restrict__ x, const float* __restrict__ W,
        float* __restrict__ out)
{
    extern __shared__ uint32_t su[];
    uint32_t* xh    = su + OFF_XH;                    // [j][tp] half2 pairs
    uint32_t* wd    = su + OFF_WD;                    // [2][j][k] dup half2
    float*    wsq_s = (float*)(su + OFF_WSQ);
    float*    xsq_s = (float*)(su + OFF_XSQ);
    unsigned long long* best = (unsigned long long*)(su + OFF_BEST);
    int*      qcount = (int*)(su + OFF_QCNT);
    int*      scount = (int*)(su + OFF_SCNT);
    uint32_t* queue  = su + OFF_QUEUE;
    int*      fidx   = (int*)(su + OFF_FIDX);
    float*    red    = (float*)(su + OFF_RED);

    const int tid   = threadIdx.x;
    const int lane  = tid & 31;
    const int wid   = tid >> 5;
    const int tbase = blockIdx.x * TT;
    const int t0    = lane * 4;       // tokens t0..t0+3
    const int k0    = wid * 8;        // this warp's 8 codes per chunk

    const uint32_t wd_u = smem_u32(wd);

    if (tid == 0) { *qcount = 0; *scount = 0; }
    if (tid < TT) best[tid] = 0xFFFFFFFFFFFFFFFFull;

    // ---- build fp16 token-pair tile xh[j][tp] ----
    for (int i = tid; i < 1024; i += NTHREADS) {
        int tp = i >> 4;                  // token pair 0..63
        int j4 = (i & 15) << 2;
        float4 va = *(const float4*)(x + (size_t)(tbase + 2 * tp) * DIM + j4);
        float4 vb = *(const float4*)(x + (size_t)(tbase + 2 * tp + 1) * DIM + j4);
        xh[(j4 + 0) * WDT_STR + tp] = h2_bits(__floats2half2_rn(va.x, vb.x));
        xh[(j4 + 1) * WDT_STR + tp] = h2_bits(__floats2half2_rn(va.y, vb.y));
        xh[(j4 + 2) * WDT_STR + tp] = h2_bits(__floats2half2_rn(va.z, vb.z));
        xh[(j4 + 3) * WDT_STR + tp] = h2_bits(__floats2half2_rn(va.w, vb.w));
    }
    for (int i = tid; i < KCODES; i += NTHREADS) wsq_s[i] = g_wsq[i];

    // ---- prefetch W chunk 0 ----
    for (int i = tid; i < 1024; i += NTHREADS) {      // 64 j x 16 segs
        int j = i >> 4, seg = i & 15;
        CP_ASYNC16(wd_u + (uint32_t)(j * WDT_STR + seg * 4) * 4,
                   g_whdT + (size_t)j * KCODES + seg * 4);
    }
    CP_COMMIT();

    // ---- xsq per token (sequential order, as R1/reference) ----
    if (tid < TT) {
        const float4* row = (const float4*)(x + (size_t)(tbase + tid) * DIM);
        float s = 0.f;
        #pragma unroll
        for (int q = 0; q < 16; ++q) {
            float4 v = row[q];
            s += v.x * v.x; s += v.y * v.y; s += v.z * v.z; s += v.w * v.w;
        }
        xsq_s[tid] = s;
    }
    __syncthreads();

    float xsqr[4];
    #pragma unroll
    for (int c = 0; c < 4; ++c) xsqr[c] = xsq_s[t0 + c];

    float rlb[4];
    #pragma unroll
    for (int c = 0; c < 4; ++c) rlb[c] = 3.0e38f;

    for (int ch = 0; ch < NCH; ++ch) {
        const int b = ch & 1;
        CP_WAIT0();
        __syncthreads();                  // chunk ch resident; counters reset

        if (ch + 1 < NCH) {               // prefetch next chunk
            const uint32_t* src = g_whdT + (size_t)(ch + 1) * CH;
            const uint32_t dst0 = wd_u + (uint32_t)(((ch + 1) & 1) * WD_BUF) * 4;
            for (int i = tid; i < 1024; i += NTHREADS) {
                int j = i >> 4, seg = i & 15;
                CP_ASYNC16(dst0 + (uint32_t)(j * WDT_STR + seg * 4) * 4,
                           src + (size_t)j * KCODES + seg * 4);
            }
            CP_COMMIT();
        }

        const uint32_t* wb = wd + b * WD_BUF + k0;

        // Split fp16 chains: L over j<32, H over j>=32 (halves accum error)
        __half2 accL[2][8], accH[2][8];
        #pragma unroll
        for (int p = 0; p < 2; ++p)
            #pragma unroll
            for (int k = 0; k < 8; ++k) {
                accL[p][k] = __floats2half2_rn(0.f, 0.f);
                accH[p][k] = __floats2half2_rn(0.f, 0.f);
            }

        #pragma unroll 8
        for (int j = 0; j < 32; ++j) {
            uint2 xv = *(const uint2*)(xh + j * WDT_STR + lane * 2);
            __half2 xp0 = bits_h2(xv.x), xp1 = bits_h2(xv.y);
            uint4 wa = *(const uint4*)(wb + (size_t)j * WDT_STR);
            uint4 wc = *(const uint4*)(wb + (size_t)j * WDT_STR + 4);
            accL[0][0] = __hfma2(bits_h2(wa.x), xp0, accL[0][0]);
            accL[1][0] = __hfma2(bits_h2(wa.x), xp1, accL[1][0]);
            accL[0][1] = __hfma2(bits_h2(wa.y), xp0, accL[0][1]);
            accL[1][1] = __hfma2(bits_h2(wa.y), xp1, accL[1][1]);
            accL[0][2] = __hfma2(bits_h2(wa.z), xp0, accL[0][2]);
            accL[1][2] = __hfma2(bits_h2(wa.z), xp1, accL[1][2]);
            accL[0][3] = __hfma2(bits_h2(wa.w), xp0, accL[0][3]);
            accL[1][3] = __hfma2(bits_h2(wa.w), xp1, accL[1][3]);
            accL[0][4] = __hfma2(bits_h2(wc.x), xp0, accL[0][4]);
            accL[1][4] = __hfma2(bits_h2(wc.x), xp1, accL[1][4]);
            accL[0][5] = __hfma2(bits_h2(wc.y), xp0, accL[0][5]);
            accL[1][5] = __hfma2(bits_h2(wc.y), xp1, accL[1][5]);
            accL[0][6] = __hfma2(bits_h2(wc.z), xp0, accL[0][6]);
            accL[1][6] = __hfma2(bits_h2(wc.z), xp1, accL[1][6]);
            accL[0][7] = __hfma2(bits_h2(wc.w), xp0, accL[0][7]);
            accL[1][7] = __hfma2(bits_h2(wc.w), xp1, accL[1][7]);
        }
        #pragma unroll 8
        for (int j = 32; j < 64; ++j) {
            uint2 xv = *(const uint2*)(xh + j * WDT_STR + lane * 2);
            __half2 xp0 = bits_h2(xv.x), xp1 = bits_h2(xv.y);
            uint4 wa = *(const uint4*)(wb + (size_t)j * WDT_STR);
            uint4 wc = *(const uint4*)(wb + (size_t)j * WDT_STR + 4);
            accH[0][0] = __hfma2(bits_h2(wa.x), xp0, accH[0][0]);
            accH[1][0] = __hfma2(bits_h2(wa.x), xp1, accH[1][0]);
            accH[0][1] = __hfma2(bits_h2(wa.y), xp0, accH[0][1]);
            accH[1][1] = __hfma2(bits_h2(wa.y), xp1, accH[1][1]);
            accH[0][2] = __hfma2(bits_h2(wa.z), xp0, accH[0][2]);
            accH[1][2] = __hfma2(bits_h2(wa.z), xp1, accH[1][2]);
            accH[0][3] = __hfma2(bits_h2(wa.w), xp0, accH[0][3]);
            accH[1][3] = __hfma2(bits_h2(wa.w), xp1, accH[1][3]);
            accH[0][4] = __hfma2(bits_h2(wc.x), xp0, accH[0][4]);
            accH[1][4] = __hfma2(bits_h2(wc.x), xp1, accH[1][4]);
            accH[0][5] = __hfma2(bits_h2(wc.y), xp0, accH[0][5]);
            accH[1][5] = __hfma2(bits_h2(wc.y), xp1, accH[1][5]);
            accH[0][6] = __hfma2(bits_h2(wc.z), xp0, accH[0][6]);
            accH[1][6] = __hfma2(bits_h2(wc.z), xp1, accH[1][6]);
            accH[0][7] = __hfma2(bits_h2(wc.w), xp0, accH[0][7]);
            accH[1][7] = __hfma2(bits_h2(wc.w), xp1, accH[1][7]);
        }

        // ---- screen: combine chains in fp32, append candidates ----
        #pragma unroll
        for (int k = 0; k < 8; ++k) {
            const int lc = k0 + k;
            const int g  = ch * CH + lc;
            const float wsqk = wsq_s[g];
            float2 l0 = __half22float2(accL[0][k]);
            float2 h0 = __half22float2(accH[0][k]);
            float2 l1 = __half22float2(accL[1][k]);
            float2 h1 = __half22float2(accH[1][k]);
            float a0 = fmaf(-2.f, l0.x + h0.x, wsqk + xsqr[0]);
            float a1 = fmaf(-2.f, l0.y + h0.y, wsqk + xsqr[1]);
            float a2 = fmaf(-2.f, l1.x + h1.x, wsqk + xsqr[2]);
            float a3 = fmaf(-2.f, l1.y + h1.y, wsqk + xsqr[3]);
            queue_append(a0 < rlb[0] + MARGIN,
                         (uint32_t)(((t0 + 0) << 8) | lc), qcount, scount, queue);
            queue_append(a1 < rlb[1] + MARGIN,
                         (uint32_t)(((t0 + 1) << 8) | lc), qcount, scount, queue);
            queue_append(a2 < rlb[2] + MARGIN,
                         (uint32_t)(((t0 + 2) << 8) | lc), qcount, scount, queue);
            queue_append(a3 < rlb[3] + MARGIN,
                         (uint32_t)(((t0 + 3) << 8) | lc), qcount, scount, queue);
            rlb[0] = fminf(rlb[0], a0);
            rlb[1] = fminf(rlb[1], a1);
            rlb[2] = fminf(rlb[2], a2);
            rlb[3] = fminf(rlb[3], a3);
        }

        __syncthreads();                  // appends visible

        // ---- cooperative bit-exact refine: smem queue, then spill ----
        const int nq = min(*qcount, QCAP);
        const int ns = min(*scount, SPILLCAP);
        for (int i = tid; i < nq + ns; i += NTHREADS) {
            uint32_t e = (i < nq) ? queue[i]
                                  : g_spill[(size_t)blockIdx.x * SPILLCAP + (i - nq)];
            int t  = (int)(e >> 8);
            int lc = (int)(e & 255);
            int g  = ch * CH + lc;
            float base = wsq_s[g] + xsq_s[t];
            float d = exact_dist(x + (size_t)(tbase + t) * DIM,
                                 W + (size_t)g * DIM, base);
            unsigned long long key =
                ((unsigned long long)__float_as_uint(d) << 32) | (uint32_t)g;
            atomicMin(&best[t], key);
        }

        __syncthreads();                  // refine done
        if (tid == 0) { *qcount = 0; *scount = 0; }
    }

    __syncthreads();
    if (tid < TT) {
        int bi = (int)(best[tid] & 0xFFFFFFFFull);
        fidx[tid] = bi;
        atomicAdd(&g_counts[bi], 1);
    }
    __syncthreads();

    // ---- epilogue: quantized_st (coalesced) + loss partial ----
    float ls = 0.f;
    for (int i = tid; i < TT * 16; i += NTHREADS) {
        int t  = i >> 4;
        int c4 = (i & 15) << 2;
        int kb = fidx[t];
        float4 w4 = *(const float4*)(W + (size_t)kb * DIM + c4);
        float4 xv = *(const float4*)(x + (size_t)(tbase + t) * DIM + c4);
        float4 o; float dq;
        dq = w4.x - xv.x; o.x = xv.x + dq; ls = fmaf(dq, dq, ls);
        dq = w4.y - xv.y; o.y = xv.y + dq; ls = fmaf(dq, dq, ls);
        dq = w4.z - xv.z; o.z = xv.z + dq; ls = fmaf(dq, dq, ls);
        dq = w4.w - xv.w; o.w = xv.w + dq; ls = fmaf(dq, dq, ls);
        *(float4*)(out + (size_t)(tbase + t) * DIM + c4) = o;
    }

    red[tid] = ls;
    __syncthreads();
    for (int off = NTHREADS / 2; off > 0; off >>= 1) {
        if (tid < off) red[tid] += red[tid + off];
        __syncthreads();
    }
    if (tid == 0) g_part[blockIdx.x] = red[0];
}

// ---------------------------------------------------------------------------
// Kernel 2: final scalars (loss, perplexity, usage)
// ---------------------------------------------------------------------------
__global__ void vq_final(float* __restrict__ out, int out_size) {
    __shared__ float red[1024];
    __shared__ float red2[1024];
    int tid = threadIdx.x;

    red[tid] = g_part[tid];
    __syncthreads();
    for (int off = 512; off > 0; off >>= 1) {
        if (tid < off) red[tid] += red[tid + off];
        __syncthreads();
    }
    float sse = red[0];
    __syncthreads();

    int c  = g_counts[tid];
    float p = (float)c / (float)N_TOK;
    red[tid]  = p * logf(p + 1e-10f);
    red2[tid] = (c >= 1) ? 1.f : 0.f;
    __syncthreads();
    for (int off = 512; off > 0; off >>= 1) {
        if (tid < off) { red[tid] += red[tid + off]; red2[tid] += red2[tid + off]; }
        __syncthreads();
    }
    if (tid == 0 && out_size >= N_TOK * DIM + 3) {
        float mse = sse / (float)(N_TOK * DIM);
        out[N_TOK * DIM + 0] = mse + 2.0f * mse;   // q_latent + COMMITMENT_COST*e_latent
        out[N_TOK * DIM + 1] = expf(-red[0]);
        out[N_TOK * DIM + 2] = red2[0];
    }
}

// ---------------------------------------------------------------------------
extern "C" void kernel_launch(void* const* d_in, const int* in_sizes, int n_in,
                              void* d_out, int out_size) {
    const float* x = (const float*)d_in[0];   // [32,4096,64] f32
    const float* W = (const float*)d_in[1];   // [1024,64] f32
    float* out = (float*)d_out;

    cudaFuncSetAttribute(vq_main, cudaFuncAttributeMaxDynamicSharedMemorySize,
                         SMEM_BYTES);

    vq_prep<<<4, 256>>>(W);
    vq_main<<<NB, NTHREADS, SMEM_BYTES>>>(x, W, out);
    vq_final<<<1, 1024>>>(out, out_size);
}